// round 14
// baseline (speedup 1.0000x reference)
#include <cuda_runtime.h>

typedef unsigned long long ull;

// Problem: X[8,256,128], W1[128,128], W2[128,128], v[128] -> out[8,256,256]
#define BB   8
#define DD   256
#define DIM  128
#define GRID 1024

// Scratch:
//  g_Ea  : [b*DD+d][m]  row-major
//  g_Ec4 : [b][g=m/4][k][m%4]  (phase B streams float4 per m-quad per thread)
__device__ float g_Ea [BB * DD * DIM];
__device__ float g_Ec4[BB * 32 * DD * 4 + 6 * DD * 4];  // pad: prefetch overrun
__device__ float g_Vsum;
__device__ unsigned g_cnt;                               // monotonic barrier ctr

// ---- packed f32x2 helpers (Blackwell) --------------------------------------
__device__ __forceinline__ ull fma2(ull a, ull b, ull c) {
    ull d; asm("fma.rn.f32x2 %0,%1,%2,%3;" : "=l"(d) : "l"(a), "l"(b), "l"(c)); return d;
}
__device__ __forceinline__ ull mul2(ull a, ull b) {
    ull d; asm("mul.rn.f32x2 %0,%1,%2;" : "=l"(d) : "l"(a), "l"(b)); return d;
}
__device__ __forceinline__ ull dup2(float x) {
    ull d; asm("mov.b64 %0,{%1,%1};" : "=l"(d) : "f"(x)); return d;
}
__device__ __forceinline__ float2 unpk(ull a) {
    float2 r; asm("mov.b64 {%0,%1},%2;" : "=f"(r.x), "=f"(r.y) : "l"(a)); return r;
}
__device__ __forceinline__ ull pk(float x, float y) {
    ull d; asm("mov.b64 %0,{%1,%2};" : "=l"(d) : "f"(x), "f"(y)); return d;
}
__device__ __forceinline__ float frcp(float x) {
    float r; asm("rcp.approx.f32 %0,%1;" : "=f"(r) : "f"(x)); return r;
}

// ---------------------------------------------------------------------------
// Fused kernel: grid = 1024 x 128 threads, occ 7 (single co-resident wave:
// 148*7 = 1036 >= 1024).
// Phase A (ALL blocks): block = 16-row x 32-m tile of one matrix.
//   GEMM tile + exp(2*), direct stores into phase-B layouts.
// One generation-counter grid barrier (replay-safe).
// Phase B: R10's pairwise loop verbatim (best measured k2).
// ---------------------------------------------------------------------------
__global__ void __launch_bounds__(128, 7) fused_pairwise(
    const float* __restrict__ X,
    const float* __restrict__ W1,
    const float* __restrict__ W2,
    const float* __restrict__ v,
    float* __restrict__ out)
{
    __shared__ __align__(16) float Ws[32 * 132];   // W tile 32m x 128k (pad 132)
    __shared__ __align__(16) float Xs[16 * DIM];   // X tile 16 rows (reused as Es)
    __shared__ __align__(16) float EaS[4 * DIM];   // phase B: [j][m]
    __shared__ __align__(16) float vS[DIM];        // phase B: v

    const int t   = threadIdx.x;
    const int bid = blockIdx.x;

    // ---------------- Phase A: GEMM tile + exp ------------------------------
    {
        const int mat  = bid & 1;
        const int mg   = (bid >> 1) & 3;
        const int rg   = bid >> 3;            // 0..127
        const int row0 = rg * 16;             // global row b*256+d (16 | 256)
        const int bA   = row0 >> 8;
        const int d0   = row0 & 255;
        const int m0   = mg * 32;
        const float* W = mat ? W2 : W1;

        vS[t] = v[t];                          // phase-B v staging (independent)

        #pragma unroll
        for (int i = 0; i < 8; i++) {          // W tile: 1024 float4
            int idx = t + i * 128;
            int wr = idx >> 5, k4 = idx & 31;
            *(float4*)&Ws[wr * 132 + k4 * 4] =
                ((const float4*)W)[(m0 + wr) * 32 + k4];
        }
        #pragma unroll
        for (int i = 0; i < 4; i++) {          // X tile: 512 float4
            int idx = t + i * 128;
            int xr = idx >> 5, k4 = idx & 31;
            *(float4*)&Xs[xr * DIM + k4 * 4] =
                ((const float4*)X)[(row0 + xr) * 32 + k4];
        }
        __syncthreads();

        const int lane = t & 31;               // m_local
        const int rq   = t >> 5;                // row quad 0..3

        ull acc[4];
        #pragma unroll
        for (int r = 0; r < 4; r++) acc[r] = dup2(0.0f);

        #pragma unroll 8
        for (int k4 = 0; k4 < 32; k4++) {
            ulonglong2 w = *(const ulonglong2*)&Ws[lane * 132 + k4 * 4];
            #pragma unroll
            for (int r = 0; r < 4; r++) {
                ulonglong2 x = *(const ulonglong2*)&Xs[(rq * 4 + r) * DIM + k4 * 4];
                acc[r] = fma2(w.x, x.x, acc[r]);
                acc[r] = fma2(w.y, x.y, acc[r]);
            }
        }

        float val[4];
        #pragma unroll
        for (int r = 0; r < 4; r++) {
            float2 a = unpk(acc[r]);
            val[r] = __expf(2.0f * (a.x + a.y));
        }

        if (mat == 0) {
            // Ea row-major: lanes m consecutive -> coalesced STG.32
            #pragma unroll
            for (int r = 0; r < 4; r++)
                g_Ea[(size_t)(row0 + rq * 4 + r) * DIM + m0 + lane] = val[r];
        } else {
            // smem transpose (reuse Xs: 32m x 16d, pad 17) -> coalesced STG.128
            float* Es = Xs;
            __syncthreads();                    // done reading Xs
            #pragma unroll
            for (int r = 0; r < 4; r++)
                Es[lane * 17 + rq * 4 + r] = val[r];
            __syncthreads();
            {
                int gl = t >> 4, kl = t & 15;   // 8 g-groups x 16 k
                float4 o;
                o.x = Es[(gl * 4 + 0) * 17 + kl];
                o.y = Es[(gl * 4 + 1) * 17 + kl];
                o.z = Es[(gl * 4 + 2) * 17 + kl];
                o.w = Es[(gl * 4 + 3) * 17 + kl];
                *(float4*)&g_Ec4[((size_t)(bA * 32 + mg * 8 + gl) * DD + d0 + kl) * 4] = o;
            }
        }

        if (bid == 0 && t < 32) {              // Vsum side-job
            float s = v[t] + v[t + 32] + v[t + 64] + v[t + 96];
            #pragma unroll
            for (int o = 16; o; o >>= 1) s += __shfl_xor_sync(0xffffffffu, s, o);
            if (t == 0) g_Vsum = s;
        }
    }

    // ---------------- Grid barrier (monotonic, replay-safe) -----------------
    __threadfence();
    __syncthreads();
    if (t == 0) {
        unsigned old = atomicAdd(&g_cnt, 1u);
        unsigned target = old - (old % GRID) + GRID;
        while ((int)(*(volatile unsigned*)&g_cnt - target) < 0)
            __nanosleep(64);
    }
    __syncthreads();

    // ---------------- Phase B: pairwise (R10 loop verbatim) -----------------
    const int kt = bid & 1;
    const int jg = (bid >> 1) & 63;
    const int b  = bid >> 7;
    const int j0 = jg * 4;
    const int k  = kt * 128 + t;

    {   // Stage 4 Ea rows (coalesced LDG.128 + linear STS.128)
        int j = t >> 5, q = t & 31;
        ((float4*)EaS)[t] =
            ((const float4*)(g_Ea + (size_t)(b * DD + j0 + j) * DIM))[q];
    }
    __syncthreads();

    const float Vsum = g_Vsum;
    const ull ONE2 = dup2(1.0f);
    ull acc0 = dup2(0.0f), acc1 = dup2(0.0f);
    ull acc2 = dup2(0.0f), acc3 = dup2(0.0f);

    const ulonglong2* __restrict__ ecq =
        (const ulonglong2*)(g_Ec4 + (size_t)b * 32 * DD * 4 + k * 4);

    ulonglong2 P0a = __ldg(ecq + 0 * DD), P0b = __ldg(ecq + 1 * DD);
    ulonglong2 P1a = __ldg(ecq + 2 * DD), P1b = __ldg(ecq + 3 * DD);

    #pragma unroll 4
    for (int gg = 0; gg < 16; gg++) {          // 8 m per iteration
        ulonglong2 Na = __ldg(ecq + (2 * gg + 4) * DD);   // padded tail
        ulonglong2 Nb = __ldg(ecq + (2 * gg + 5) * DD);

        ulonglong2 vA = *(const ulonglong2*)&vS[8 * gg];      // (v01),(v23)
        ulonglong2 vB = *(const ulonglong2*)&vS[8 * gg + 4];  // (v45),(v67)

        #pragma unroll
        for (int j = 0; j < 4; j++) {
            ulonglong2 A0 = *(const ulonglong2*)&EaS[j * DIM + 8 * gg];
            ulonglong2 A1 = *(const ulonglong2*)&EaS[j * DIM + 8 * gg + 4];
            ull q01 = fma2(A0.x, P0a.x, ONE2);
            ull q23 = fma2(A0.y, P0a.y, ONE2);
            ull q45 = fma2(A1.x, P0b.x, ONE2);
            ull q67 = fma2(A1.y, P0b.y, ONE2);
            ull d03 = mul2(q01, q23);
            ull d47 = mul2(q45, q67);
            ull n03 = mul2(vA.x, q23); n03 = fma2(vA.y, q01, n03);
            ull n47 = mul2(vB.x, q67); n47 = fma2(vB.y, q45, n47);
            ull den = mul2(d03, d47);
            ull num = mul2(n03, d47); num = fma2(n47, d03, num);
            float2 dd = unpk(den);
            ull rr = pk(frcp(dd.x), frcp(dd.y));     // 1 rcp-lane per 4 m
            if      (j == 0) acc0 = fma2(num, rr, acc0);
            else if (j == 1) acc1 = fma2(num, rr, acc1);
            else if (j == 2) acc2 = fma2(num, rr, acc2);
            else             acc3 = fma2(num, rr, acc3);
        }
        P0a = P1a; P0b = P1b;
        P1a = Na;  P1b = Nb;
    }

    // Epilogue: lane-sum + direct coalesced stores (lanes k consecutive)
    float* ob = out + (size_t)(b * DD + j0) * DD + k;
    float2 u0 = unpk(acc0), u1 = unpk(acc1), u2 = unpk(acc2), u3 = unpk(acc3);
    ob[0 * DD] = fmaf(-2.0f, u0.x + u0.y, Vsum);
    ob[1 * DD] = fmaf(-2.0f, u1.x + u1.y, Vsum);
    ob[2 * DD] = fmaf(-2.0f, u2.x + u2.y, Vsum);
    ob[3 * DD] = fmaf(-2.0f, u3.x + u3.y, Vsum);
}

// ---------------------------------------------------------------------------
extern "C" void kernel_launch(void* const* d_in, const int* in_sizes, int n_in,
                              void* d_out, int out_size)
{
    const float* X  = (const float*)d_in[0];
    const float* W1 = (const float*)d_in[1];
    const float* W2 = (const float*)d_in[2];
    const float* v  = (const float*)d_in[3];
    float* out      = (float*)d_out;

    fused_pairwise<<<GRID, 128>>>(X, W1, W2, v, out);
}

// round 15
// speedup vs baseline: 1.1322x; 1.1322x over previous
#include <cuda_runtime.h>

typedef unsigned long long ull;

// Problem: X[8,256,128], W1[128,128], W2[128,128], v[128] -> out[8,256,256]
#define BB   8
#define DD   256
#define DIM  128

// Scratch:
//  g_Ea  : [b*DD+d][m]  row-major (k2 stages rows coalesced)
//  g_Ec4 : [b][g=m/4][k][m%4]  (k2 streams float4 per m-quad per thread)
__device__ float g_Ea [BB * DD * DIM];
__device__ float g_Ec4[BB * 32 * DD * 4 + 6 * DD * 4];  // pad: prefetch overrun
__device__ float g_Vsum;

// ---- packed f32x2 helpers (Blackwell) --------------------------------------
__device__ __forceinline__ ull fma2(ull a, ull b, ull c) {
    ull d; asm("fma.rn.f32x2 %0,%1,%2,%3;" : "=l"(d) : "l"(a), "l"(b), "l"(c)); return d;
}
__device__ __forceinline__ ull mul2(ull a, ull b) {
    ull d; asm("mul.rn.f32x2 %0,%1,%2;" : "=l"(d) : "l"(a), "l"(b)); return d;
}
__device__ __forceinline__ ull dup2(float x) {
    ull d; asm("mov.b64 %0,{%1,%1};" : "=l"(d) : "f"(x)); return d;
}
__device__ __forceinline__ float2 unpk(ull a) {
    float2 r; asm("mov.b64 {%0,%1},%2;" : "=f"(r.x), "=f"(r.y) : "l"(a)); return r;
}
__device__ __forceinline__ ull pk(float x, float y) {
    ull d; asm("mov.b64 %0,{%1,%2};" : "=l"(d) : "f"(x), "f"(y)); return d;
}
__device__ __forceinline__ float frcp(float x) {
    float r; asm("rcp.approx.f32 %0,%1;" : "=f"(r) : "f"(x)); return r;
}

// ---------------------------------------------------------------------------
// Kernel 1: grid = 1024 (128 row-groups x 4 m-groups x 2 mats), 128 threads,
// occ 8 (25KB smem). Block = 16-row x 32-m GEMM tile + exp(2*).
// Fine tiles -> all 148 SMs busy, tiny staging bursts, high warp count.
// mat 0: Ea row-major direct (coalesced). mat 1: Ec via pad-17 smem
// transpose -> coalesced STG.128. Block 0 computes g_Vsum.
// ---------------------------------------------------------------------------
__global__ void __launch_bounds__(128, 8) k1_gemm_exp(
    const float* __restrict__ X,
    const float* __restrict__ W1,
    const float* __restrict__ W2,
    const float* __restrict__ v)
{
    __shared__ __align__(16) float Ws[32 * 132];   // W tile 32m x 128k (pad 132)
    __shared__ __align__(16) float Xs[16 * DIM];   // X tile 16 rows (reused as Es)

    const int t    = threadIdx.x;
    const int bid  = blockIdx.x;
    const int mat  = bid & 1;
    const int mg   = (bid >> 1) & 3;
    const int rg   = bid >> 3;             // 0..127
    const int row0 = rg * 16;              // global row b*256+d  (16 | 256)
    const int bA   = row0 >> 8;
    const int d0   = row0 & 255;
    const int m0   = mg * 32;
    const float* W = mat ? W2 : W1;

    if (bid == 0 && t < 32) {              // Vsum side-job
        float s = v[t] + v[t + 32] + v[t + 64] + v[t + 96];
        #pragma unroll
        for (int o = 16; o; o >>= 1) s += __shfl_xor_sync(0xffffffffu, s, o);
        if (t == 0) g_Vsum = s;
    }

    #pragma unroll
    for (int i = 0; i < 8; i++) {          // W tile: 1024 float4
        int idx = t + i * 128;
        int wr = idx >> 5, k4 = idx & 31;
        *(float4*)&Ws[wr * 132 + k4 * 4] =
            ((const float4*)W)[(m0 + wr) * 32 + k4];
    }
    #pragma unroll
    for (int i = 0; i < 4; i++) {          // X tile: 512 float4
        int idx = t + i * 128;
        int xr = idx >> 5, k4 = idx & 31;
        *(float4*)&Xs[xr * DIM + k4 * 4] =
            ((const float4*)X)[(row0 + xr) * 32 + k4];
    }
    __syncthreads();

    const int lane = t & 31;               // m_local
    const int rq   = t >> 5;               // row quad 0..3

    ull acc[4];
    #pragma unroll
    for (int r = 0; r < 4; r++) acc[r] = dup2(0.0f);

    #pragma unroll 8
    for (int k4 = 0; k4 < 32; k4++) {
        ulonglong2 w = *(const ulonglong2*)&Ws[lane * 132 + k4 * 4];
        #pragma unroll
        for (int r = 0; r < 4; r++) {
            ulonglong2 x = *(const ulonglong2*)&Xs[(rq * 4 + r) * DIM + k4 * 4];
            acc[r] = fma2(w.x, x.x, acc[r]);
            acc[r] = fma2(w.y, x.y, acc[r]);
        }
    }

    float val[4];
    #pragma unroll
    for (int r = 0; r < 4; r++) {
        float2 a = unpk(acc[r]);
        val[r] = __expf(2.0f * (a.x + a.y));
    }

    if (mat == 0) {
        // Ea row-major: lanes m consecutive -> coalesced STG.32
        #pragma unroll
        for (int r = 0; r < 4; r++)
            g_Ea[(size_t)(row0 + rq * 4 + r) * DIM + m0 + lane] = val[r];
    } else {
        // smem transpose (reuse Xs: 32m x 16d, pad 17) -> coalesced STG.128
        float* Es = Xs;
        __syncthreads();                    // done reading Xs
        #pragma unroll
        for (int r = 0; r < 4; r++)
            Es[lane * 17 + rq * 4 + r] = val[r];
        __syncthreads();
        {
            int gl = t >> 4, kl = t & 15;   // 8 m-quads x 16 k
            float4 o;
            o.x = Es[(gl * 4 + 0) * 17 + kl];
            o.y = Es[(gl * 4 + 1) * 17 + kl];
            o.z = Es[(gl * 4 + 2) * 17 + kl];
            o.w = Es[(gl * 4 + 3) * 17 + kl];
            *(float4*)&g_Ec4[((size_t)(bA * 32 + mg * 8 + gl) * DD + d0 + kl) * 4] = o;
        }
    }

    cudaTriggerProgrammaticLaunchCompletion();
}

// ---------------------------------------------------------------------------
// Kernel 2 (PDL secondary): R10 verbatim — best measured configuration.
// grid = 1024 (8b x 64jg x 2kt), 128 threads, occ 7. Thread = 1 k, 4 j;
// f32x2 lanes packed over ADJACENT M; 2-deep Ec register pipeline;
// 8 m / iter; 1 rcp-instr per 4 m via 4-way rational combine.
// ---------------------------------------------------------------------------
__global__ void __launch_bounds__(128, 7) k2_pairwise(
    const float* __restrict__ v,
    float* __restrict__ out)
{
    __shared__ __align__(16) float EaS[4 * DIM];   // [j][m] row-major
    __shared__ __align__(16) float vS[DIM];

    const int t   = threadIdx.x;
    const int bid = blockIdx.x;
    const int kt  = bid & 1;
    const int jg  = (bid >> 1) & 63;
    const int b   = bid >> 7;
    const int j0  = jg * 4;
    const int k   = kt * 128 + t;

    // k1-independent prologue (overlaps k1 under PDL)
    vS[t] = v[t];

    cudaGridDependencySynchronize();

    {   // Stage 4 Ea rows (coalesced LDG.128 + linear STS.128)
        int j = t >> 5, q = t & 31;
        ((float4*)EaS)[t] =
            ((const float4*)(g_Ea + (size_t)(b * DD + j0 + j) * DIM))[q];
    }
    __syncthreads();

    const float Vsum = g_Vsum;
    const ull ONE2 = dup2(1.0f);
    ull acc0 = dup2(0.0f), acc1 = dup2(0.0f);
    ull acc2 = dup2(0.0f), acc3 = dup2(0.0f);

    const ulonglong2* __restrict__ ecq =
        (const ulonglong2*)(g_Ec4 + (size_t)b * 32 * DD * 4 + k * 4);

    ulonglong2 P0a = __ldg(ecq + 0 * DD), P0b = __ldg(ecq + 1 * DD);
    ulonglong2 P1a = __ldg(ecq + 2 * DD), P1b = __ldg(ecq + 3 * DD);

    #pragma unroll 4
    for (int gg = 0; gg < 16; gg++) {          // 8 m per iteration
        ulonglong2 Na = __ldg(ecq + (2 * gg + 4) * DD);   // padded tail
        ulonglong2 Nb = __ldg(ecq + (2 * gg + 5) * DD);

        ulonglong2 vA = *(const ulonglong2*)&vS[8 * gg];      // (v01),(v23)
        ulonglong2 vB = *(const ulonglong2*)&vS[8 * gg + 4];  // (v45),(v67)

        #pragma unroll
        for (int j = 0; j < 4; j++) {
            ulonglong2 A0 = *(const ulonglong2*)&EaS[j * DIM + 8 * gg];
            ulonglong2 A1 = *(const ulonglong2*)&EaS[j * DIM + 8 * gg + 4];
            ull q01 = fma2(A0.x, P0a.x, ONE2);
            ull q23 = fma2(A0.y, P0a.y, ONE2);
            ull q45 = fma2(A1.x, P0b.x, ONE2);
            ull q67 = fma2(A1.y, P0b.y, ONE2);
            ull d03 = mul2(q01, q23);
            ull d47 = mul2(q45, q67);
            ull n03 = mul2(vA.x, q23); n03 = fma2(vA.y, q01, n03);
            ull n47 = mul2(vB.x, q67); n47 = fma2(vB.y, q45, n47);
            ull den = mul2(d03, d47);
            ull num = mul2(n03, d47); num = fma2(n47, d03, num);
            float2 dd = unpk(den);
            ull rr = pk(frcp(dd.x), frcp(dd.y));     // 1 rcp-lane per 4 m
            if      (j == 0) acc0 = fma2(num, rr, acc0);
            else if (j == 1) acc1 = fma2(num, rr, acc1);
            else if (j == 2) acc2 = fma2(num, rr, acc2);
            else             acc3 = fma2(num, rr, acc3);
        }
        P0a = P1a; P0b = P1b;
        P1a = Na;  P1b = Nb;
    }

    // Epilogue: lane-sum + direct coalesced stores (lanes k consecutive)
    float* ob = out + (size_t)(b * DD + j0) * DD + k;
    float2 u0 = unpk(acc0), u1 = unpk(acc1), u2 = unpk(acc2), u3 = unpk(acc3);
    ob[0 * DD] = fmaf(-2.0f, u0.x + u0.y, Vsum);
    ob[1 * DD] = fmaf(-2.0f, u1.x + u1.y, Vsum);
    ob[2 * DD] = fmaf(-2.0f, u2.x + u2.y, Vsum);
    ob[3 * DD] = fmaf(-2.0f, u3.x + u3.y, Vsum);
}

// ---------------------------------------------------------------------------
extern "C" void kernel_launch(void* const* d_in, const int* in_sizes, int n_in,
                              void* d_out, int out_size)
{
    const float* X  = (const float*)d_in[0];
    const float* W1 = (const float*)d_in[1];
    const float* W2 = (const float*)d_in[2];
    const float* v  = (const float*)d_in[3];
    float* out      = (float*)d_out;

    k1_gemm_exp<<<1024, 128>>>(X, W1, W2, v);

    cudaLaunchAttribute attr[1];
    attr[0].id = cudaLaunchAttributeProgrammaticStreamSerialization;
    attr[0].val.programmaticStreamSerializationAllowed = 1;
    cudaLaunchConfig_t cfg = {};
    cfg.gridDim  = dim3(1024, 1, 1);
    cfg.blockDim = dim3(128, 1, 1);
    cfg.dynamicSmemBytes = 0;
    cfg.stream = 0;
    cfg.attrs = attr;
    cfg.numAttrs = 1;
    cudaLaunchKernelEx(&cfg, k2_pairwise, v, out);
}